// round 12
// baseline (speedup 1.0000x reference)
#include <cuda_runtime.h>
#include <cuda_fp16.h>
#include <mma.h>
#include <math.h>

using namespace nvcuda;

#define NMAX   100000
#define EMAX   1600000
#define SCAN_B 512

// Static scratch ~59 MB.
__device__ float g_y[(size_t)NMAX * 128];   // persistent feature buffer
__device__ float g_dinv[NMAX];
__device__ int   g_dc[2 * NMAX];            // [0:N) deg, [N:2N) cursor
__device__ int   g_rowptr[NMAX];
__device__ int   g_csr[EMAX];
__device__ volatile unsigned long long g_bdesc[256];  // lookback descriptors: flag<<32 | value
// split-fp16 weights (hi + lo residual)
__device__ __half g_w2h[128 * 64], g_w2l[128 * 64];
__device__ __half g_w3h[64 * 64],  g_w3l[64 * 64];

// ---------------- degree count + weight convert + lookback-state zero ----------------
__global__ void k_deg_count(const int* __restrict__ dst, int E,
                            const float* __restrict__ W2, const float* __restrict__ W3) {
    int e = blockIdx.x * blockDim.x + threadIdx.x;
    if (e < E) atomicAdd(&g_dc[__ldg(dst + e)], 1);
    if (blockIdx.x < 32) {
        int i = blockIdx.x * blockDim.x + threadIdx.x;
        if (i < 128 * 64) {
            float w = W2[i];
            __half h = __float2half_rn(w);
            g_w2h[i] = h;
            g_w2l[i] = __float2half_rn(w - __half2float(h));
        }
        if (i < 64 * 64) {
            float w = W3[i];
            __half h = __float2half_rn(w);
            g_w3h[i] = h;
            g_w3l[i] = __float2half_rn(w - __half2float(h));
        }
    }
    if (blockIdx.x == 40 && threadIdx.x < 256) g_bdesc[threadIdx.x] = 0ULL;
}

// ---------------- single-pass scan (decoupled lookback) + dinv + xscale + cursor0 ----------------
__global__ void k_scan_lb(const float* __restrict__ x, __half2* __restrict__ xs, int n) {
    __shared__ int wsum[SCAN_B / 32];
    __shared__ int s_excl;
    const int bid = blockIdx.x;
    const int gid = bid * SCAN_B + threadIdx.x;
    const int lane = threadIdx.x & 31, wid = threadIdx.x >> 5;

    int v = (gid < n) ? g_dc[gid] : 0;
    int incl = v;
#pragma unroll
    for (int o = 1; o < 32; o <<= 1) {
        int t = __shfl_up_sync(0xffffffffu, incl, o);
        if (lane >= o) incl += t;
    }
    if (lane == 31) wsum[wid] = incl;
    __syncthreads();
    if (wid == 0) {
        int s = (lane < SCAN_B / 32) ? wsum[lane] : 0;
#pragma unroll
        for (int o = 1; o < SCAN_B / 32; o <<= 1) {
            int t = __shfl_up_sync(0xffffffffu, s, o);
            if (lane >= o) s += t;
        }
        if (lane < SCAN_B / 32) wsum[lane] = s;
    }
    __syncthreads();
    const int blockTotal = wsum[SCAN_B / 32 - 1];
    const int off = wid ? wsum[wid - 1] : 0;

    // publish + lookback (warp 0)
    if (wid == 0) {
        if (bid == 0) {
            if (lane == 0) {
                g_bdesc[0] = (2ULL << 32) | (unsigned)blockTotal;  // inclusive
                s_excl = 0;
            }
        } else {
            if (lane == 0)
                g_bdesc[bid] = (1ULL << 32) | (unsigned)blockTotal;  // aggregate
            int excl = 0;
            int windowEnd = bid - 1;
            while (true) {
                int p = windowEnd - lane;
                unsigned long long d = (p >= 0) ? g_bdesc[p] : (2ULL << 32);
                int flag = (int)(d >> 32);
                int val = (int)(d & 0xffffffffULL);
                unsigned notReady = __ballot_sync(0xffffffffu, flag == 0);
                unsigned hasPre = __ballot_sync(0xffffffffu, flag == 2);
                int firstP = hasPre ? (__ffs(hasPre) - 1) : 32;
                int firstNR = notReady ? (__ffs(notReady) - 1) : 32;
                if (firstP < 32 && firstNR > firstP) {
                    int contrib = (lane < firstP) ? val : (lane == firstP ? val : 0);
                    excl += __reduce_add_sync(0xffffffffu, contrib);
                    break;
                } else if (firstNR == 32 && firstP == 32) {
                    excl += __reduce_add_sync(0xffffffffu, val);
                    windowEnd -= 32;
                }
            }
            if (lane == 0) {
                s_excl = excl;
                g_bdesc[bid] = (2ULL << 32) | (unsigned)(excl + blockTotal);
            }
        }
    }
    __syncthreads();

    if (gid < n) {
        g_rowptr[gid] = s_excl + off + incl - v;  // exclusive prefix
        g_dc[NMAX + gid] = 0;                     // cursor zero (for k_place)
        float dv = rsqrtf((float)(v + 1));        // +1 self loop
        g_dinv[gid] = dv;
        float vv[16];
#pragma unroll
        for (int c = 0; c < 13; ++c) vv[c] = x[(size_t)gid * 13 + c] * dv;
#pragma unroll
        for (int c = 13; c < 16; ++c) vv[c] = 0.0f;
#pragma unroll
        for (int p = 0; p < 8; ++p)
            xs[(size_t)gid * 8 + p] = __floats2half2_rn(vv[2 * p], vv[2 * p + 1]);
    }
}

// ---------------- CSR placement ----------------
__global__ void k_place(const int* __restrict__ src, const int* __restrict__ dst, int E) {
    int e = blockIdx.x * blockDim.x + threadIdx.x;
    if (e >= E) return;
    int d = __ldg(dst + e);
    int pos = g_rowptr[d] + atomicAdd(&g_dc[NMAX + d], 1);
    g_csr[pos] = __ldg(src + e);
}

// ---------------- 13(16)-ch aggregation, fp16 rows, 4 neighbors/step ----------------
__global__ void k_agg13(const __half2* __restrict__ xs, float* __restrict__ xa, int n) {
    int node = blockIdx.x * (blockDim.x >> 5) + (threadIdx.x >> 5);
    int lane = threadIdx.x & 31;
    if (node >= n) return;
    const int qw = lane >> 3;
    const int cl = lane & 7;

    float ax = 0.0f, ay = 0.0f;
    if (qw == 0) {
        float2 f = __half22float2(xs[node * 8 + cl]);
        ax = f.x; ay = f.y;
    }
    int start = g_rowptr[node];
    int end = start + g_dc[node];

    for (int j0 = start; j0 < end; j0 += 32) {
        int idx = 0;
        if (j0 + lane < end) idx = __ldg(&g_csr[j0 + lane]);
        int cnt = min(32, end - j0);
        int t = 0;
        for (; t + 8 <= cnt; t += 8) {
            int s0 = __shfl_sync(0xffffffffu, idx, t + qw);
            int s1 = __shfl_sync(0xffffffffu, idx, t + 4 + qw);
            float2 v0 = __half22float2(__ldg(&xs[s0 * 8 + cl]));
            float2 v1 = __half22float2(__ldg(&xs[s1 * 8 + cl]));
            ax += v0.x + v1.x;
            ay += v0.y + v1.y;
        }
        for (; t + 4 <= cnt; t += 4) {
            int s = __shfl_sync(0xffffffffu, idx, t + qw);
            float2 v = __half22float2(__ldg(&xs[s * 8 + cl]));
            ax += v.x; ay += v.y;
        }
        int rem = cnt - t;
        if (rem > 0) {
            int s = __shfl_sync(0xffffffffu, idx, t + (qw < rem ? qw : 0));
            if (qw < rem) {
                float2 v = __half22float2(__ldg(&xs[s * 8 + cl]));
                ax += v.x; ay += v.y;
            }
        }
    }
    ax += __shfl_down_sync(0xffffffffu, ax, 16);
    ay += __shfl_down_sync(0xffffffffu, ay, 16);
    ax += __shfl_down_sync(0xffffffffu, ax, 8);
    ay += __shfl_down_sync(0xffffffffu, ay, 8);
    if (lane < 8) {
        float dv = g_dinv[node];
        *(float2*)&xa[node * 16 + cl * 2] = make_float2(ax * dv, ay * dv);
    }
}

// ---------------- layer-1 scalar GEMM (fp32 in, fp16 out, bias+relu) ----------------
__global__ void k_gemm_l1(const float* __restrict__ x,
                          const float* __restrict__ W,
                          const float* __restrict__ bias,
                          __half* __restrict__ hout, int n) {
    constexpr int TB = 256, CIN = 13, COUT = 128, ROWS = 32, ITER = 8;
    constexpr int CPT = COUT / 16;  // 8
    constexpr int SXS = 20;
    __shared__ float Ws[CIN * COUT];
    __shared__ float xs[ROWS * SXS];

    {
        const float4* Wv = (const float4*)W;
        for (int i = threadIdx.x; i < CIN * COUT / 4; i += TB)
            ((float4*)Ws)[i] = Wv[i];
    }
    const int cg = threadIdx.x & 15;
    const int rg = threadIdx.x >> 4;
    float bb[CPT];
#pragma unroll
    for (int j = 0; j < CPT; ++j) bb[j] = __ldg(bias + cg * CPT + j);

    for (int it = 0; it < ITER; ++it) {
        const int rowbase = (blockIdx.x * ITER + it) * ROWS;
        if (rowbase >= n) break;
        float acc[2][CPT];
#pragma unroll
        for (int j = 0; j < CPT; ++j) { acc[0][j] = bb[j]; acc[1][j] = bb[j]; }

        __syncthreads();
        for (int i = threadIdx.x; i < ROWS * CIN; i += TB) {
            int row = i / CIN, c = i % CIN;
            int rr = rowbase + row;
            xs[row * SXS + c] = (rr < n) ? x[(size_t)rr * 16 + c] : 0.0f;
        }
        __syncthreads();
        const float* wbase = Ws + cg * CPT;
        const float* x0 = xs + (2 * rg) * SXS;
        const float* x1 = x0 + SXS;
#pragma unroll
        for (int k = 0; k < CIN; ++k) {
            float a0 = x0[k], a1 = x1[k];
            const float4* wr = (const float4*)(wbase + k * COUT);
#pragma unroll
            for (int j4 = 0; j4 < CPT / 4; ++j4) {
                float4 w = wr[j4];
                acc[0][j4 * 4 + 0] = fmaf(a0, w.x, acc[0][j4 * 4 + 0]);
                acc[0][j4 * 4 + 1] = fmaf(a0, w.y, acc[0][j4 * 4 + 1]);
                acc[0][j4 * 4 + 2] = fmaf(a0, w.z, acc[0][j4 * 4 + 2]);
                acc[0][j4 * 4 + 3] = fmaf(a0, w.w, acc[0][j4 * 4 + 3]);
                acc[1][j4 * 4 + 0] = fmaf(a1, w.x, acc[1][j4 * 4 + 0]);
                acc[1][j4 * 4 + 1] = fmaf(a1, w.y, acc[1][j4 * 4 + 1]);
                acc[1][j4 * 4 + 2] = fmaf(a1, w.z, acc[1][j4 * 4 + 2]);
                acc[1][j4 * 4 + 3] = fmaf(a1, w.w, acc[1][j4 * 4 + 3]);
            }
        }
#pragma unroll
        for (int rr = 0; rr < 2; ++rr) {
            int r = rowbase + 2 * rg + rr;
            if (r >= n) continue;
            __half2* hp = (__half2*)(hout + (size_t)r * 128 + cg * CPT);
#pragma unroll
            for (int j2 = 0; j2 < CPT / 2; ++j2)
                hp[j2] = __floats2half2_rn(fmaxf(acc[rr][j2 * 2], 0.0f),
                                           fmaxf(acc[rr][j2 * 2 + 1], 0.0f));
        }
    }
}

// ---------------- tensor-core GEMM (fp16 in, split-fp16 W, fp32 acc, fp16*dinv out) ----------------
template <int CIN>
__global__ void k_gemm_tc(const __half* __restrict__ A, int lda,
                          const __half* __restrict__ Whi, const __half* __restrict__ Wlo,
                          __half* __restrict__ hout, int ldo, int n) {
    constexpr int KT = CIN / 16;
    constexpr int WS_BYTES = 2 * CIN * 64 * 2;
    constexpr int EP_BYTES = 8 * 16 * 68 * 4;
    constexpr int SM_BYTES = (WS_BYTES > EP_BYTES) ? WS_BYTES : EP_BYTES;
    __shared__ __align__(16) unsigned char smem_raw[SM_BYTES];
    __half* Ws = (__half*)smem_raw;
    float* ep = (float*)smem_raw;

    for (int i = threadIdx.x; i < CIN * 64; i += 256) {
        Ws[i] = Whi[i];
        Ws[CIN * 64 + i] = Wlo[i];
    }
    __syncthreads();

    const int warp = threadIdx.x >> 5;
    const int lane = threadIdx.x & 31;
    const int rowbase = blockIdx.x * 128 + warp * 16;

    wmma::fragment<wmma::accumulator, 16, 16, 16, float> acc[4];
#pragma unroll
    for (int nt = 0; nt < 4; ++nt) wmma::fill_fragment(acc[nt], 0.0f);

    if (rowbase < n) {
#pragma unroll
        for (int kt = 0; kt < KT; ++kt) {
            wmma::fragment<wmma::matrix_a, 16, 16, 16, __half, wmma::row_major> af;
            wmma::load_matrix_sync(af, A + (size_t)rowbase * lda + kt * 16, lda);
#pragma unroll
            for (int nt = 0; nt < 4; ++nt) {
                wmma::fragment<wmma::matrix_b, 16, 16, 16, __half, wmma::row_major> bh, bl;
                wmma::load_matrix_sync(bh, Ws + kt * 16 * 64 + nt * 16, 64);
                wmma::mma_sync(acc[nt], af, bh, acc[nt]);
                wmma::load_matrix_sync(bl, Ws + CIN * 64 + kt * 16 * 64 + nt * 16, 64);
                wmma::mma_sync(acc[nt], af, bl, acc[nt]);
            }
        }
    }
    __syncthreads();

    float* myep = ep + warp * 16 * 68;
#pragma unroll
    for (int nt = 0; nt < 4; ++nt)
        wmma::store_matrix_sync(myep + nt * 16, acc[nt], 68, wmma::mem_row_major);
    __syncwarp();

    if (rowbase < n) {
#pragma unroll
        for (int r = 0; r < 16; ++r) {
            int gr = rowbase + r;
            if (gr >= n) break;
            float dv = g_dinv[gr];
            float vx = myep[r * 68 + lane * 2];
            float vy = myep[r * 68 + lane * 2 + 1];
            ((__half2*)(hout + (size_t)gr * ldo))[lane] = __floats2half2_rn(vx * dv, vy * dv);
        }
    }
}

// ---------------- 64-ch aggregation, 2 nodes/warp (half-warp each), fp32 accumulate ----------------
// y[d] = dinv[d]*(hs[d] + sum hs[s]) + b ; lane owns 4 channels (uint2 = 2x half2).
template <bool RELU, bool OUT_HALF>
__global__ void k_aggh2(const uint2* __restrict__ hs,
                        const float* __restrict__ b,
                        void* __restrict__ yout, int n) {
    const int warp = threadIdx.x >> 5;
    const int lane = threadIdx.x & 31;
    const int half = lane >> 4;   // which node of the pair
    const int hl = lane & 15;     // lane within half: channels [4*hl, 4*hl+4)
    const int node = (blockIdx.x * (blockDim.x >> 5) + warp) * 2 + half;
    const bool active = node < n;

    float ax0 = 0, ay0 = 0, ax1 = 0, ay1 = 0;
    int start = 0, deg = 0;
    if (active) {
        uint2 u = __ldg(&hs[(size_t)node * 16 + hl]);
        float2 f0 = __half22float2(*(__half2*)&u.x);
        float2 f1 = __half22float2(*(__half2*)&u.y);
        ax0 = f0.x; ay0 = f0.y; ax1 = f1.x; ay1 = f1.y;
        start = g_rowptr[node];
        deg = g_dc[node];
    }
    const int end = start + deg;
    const int myB = (deg + 15) >> 4;
    const int otherB = __shfl_xor_sync(0xffffffffu, myB, 16);
    const int wb = myB > otherB ? myB : otherB;

    for (int bt = 0; bt < wb; ++bt) {
        int j0 = start + (bt << 4);
        bool haveBatch = bt < myB;
        int cnt = haveBatch ? min(16, end - j0) : 0;
        int idx = 0;
        if (hl < cnt) idx = __ldg(&g_csr[j0 + hl]);
#pragma unroll
        for (int u8 = 0; u8 < 2; ++u8) {
            uint2 uu[8];
            bool take[8];
#pragma unroll
            for (int u = 0; u < 8; ++u) {
                int s = __shfl_sync(0xffffffffu, idx, u8 * 8 + u, 16);
                take[u] = (u8 * 8 + u) < cnt;
                if (take[u]) uu[u] = __ldg(&hs[(size_t)s * 16 + hl]);
            }
#pragma unroll
            for (int u = 0; u < 8; ++u) {
                if (take[u]) {
                    float2 f0 = __half22float2(*(__half2*)&uu[u].x);
                    float2 f1 = __half22float2(*(__half2*)&uu[u].y);
                    ax0 += f0.x; ay0 += f0.y; ax1 += f1.x; ay1 += f1.y;
                }
            }
            if (cnt <= 8) break;
        }
    }

    if (active) {
        float dv = g_dinv[node];
        float4 bb = *(const float4*)(b + hl * 4);
        float o0 = fmaf(ax0, dv, bb.x);
        float o1 = fmaf(ay0, dv, bb.y);
        float o2 = fmaf(ax1, dv, bb.z);
        float o3 = fmaf(ay1, dv, bb.w);
        if (RELU) {
            o0 = fmaxf(o0, 0.0f); o1 = fmaxf(o1, 0.0f);
            o2 = fmaxf(o2, 0.0f); o3 = fmaxf(o3, 0.0f);
        }
        if (OUT_HALF) {
            uint2 w;
            *(__half2*)&w.x = __floats2half2_rn(o0, o1);
            *(__half2*)&w.y = __floats2half2_rn(o2, o3);
            ((uint2*)yout)[(size_t)node * 16 + hl] = w;
        } else {
            *(float4*)&((float*)yout)[(size_t)node * 64 + hl * 4] =
                make_float4(o0, o1, o2, o3);
        }
    }
}

// ---------------- launch ----------------
extern "C" void kernel_launch(void* const* d_in, const int* in_sizes, int n_in,
                              void* d_out, int out_size) {
    const float* x  = (const float*)d_in[0];
    const int*   ei = (const int*)d_in[1];
    const float* W1 = (const float*)d_in[2];
    const float* b1 = (const float*)d_in[3];
    const float* W2 = (const float*)d_in[4];
    const float* b2 = (const float*)d_in[5];
    const float* W3 = (const float*)d_in[6];
    const float* b3 = (const float*)d_in[7];
    float* dout = (float*)d_out;

    const int n = in_sizes[0] / 13;
    const int E = in_sizes[1] / 2;
    const int* src = ei;
    const int* dst = ei + E;

    const int TB = 256;
    auto cdiv = [](long long a, long long b) { return (int)((a + b - 1) / b); };
    const int g_agg13g = cdiv(n, TB / 32);
    const int g_agg2g = cdiv(n, 2 * (TB / 32));  // 2 nodes per warp
    const int g_tc = cdiv(n, 128);
    const int nb = cdiv(n, SCAN_B);

    float* y = nullptr;
    cudaGetSymbolAddress((void**)&y, g_y);
    int* dcp = nullptr;
    cudaGetSymbolAddress((void**)&dcp, g_dc);
    __half *w2h, *w2l, *w3h, *w3l;
    cudaGetSymbolAddress((void**)&w2h, g_w2h);
    cudaGetSymbolAddress((void**)&w2l, g_w2l);
    cudaGetSymbolAddress((void**)&w3h, g_w3h);
    cudaGetSymbolAddress((void**)&w3l, g_w3l);

    // Buffer plan (sequential stream, dead-before-overwrite):
    __half2* xs_h2 = (__half2*)dout;                    // N x 8 half2
    float*   xa    = dout + (size_t)n * 8;              // N x 16 fp32
    __half*  y1h   = (__half*)y;                        // N x 128 fp16
    __half*  hs2   = (__half*)dout;                     // N x 64 fp16
    __half*  y2h   = (__half*)(y + (size_t)NMAX * 64);  // N x 64 fp16
    __half*  hs3   = (__half*)y;                        // N x 64 fp16 (over dead y1h)

    // ---- CSR build (4 nodes) ----
    cudaMemsetAsync(dcp, 0, (size_t)NMAX * 4, 0);           // 1 (deg only)
    k_deg_count<<<cdiv(E, TB), TB>>>(dst, E, W2, W3);       // 2 (+wconv, +bdesc zero)
    k_scan_lb<<<nb, SCAN_B>>>(x, xs_h2, n);                 // 3 (+dinv, +xscale, +cursor0)
    k_place<<<cdiv(E, TB), TB>>>(src, dst, E);              // 4

    // ---- layer 1 ----
    k_agg13<<<g_agg13g, TB>>>(xs_h2, xa, n);                // 5
    k_gemm_l1<<<cdiv(n, 32 * 8), TB>>>(xa, W1, b1, y1h, n); // 6

    // ---- layer 2 ----
    k_gemm_tc<128><<<g_tc, TB>>>(y1h, 128, w2h, w2l, hs2, 64, n);                 // 7
    k_aggh2<true, true><<<g_agg2g, TB>>>((const uint2*)hs2, b2, y2h, n);          // 8

    // ---- layer 3 ----
    k_gemm_tc<64><<<g_tc, TB>>>(y2h, 64, w3h, w3l, hs3, 64, n);                   // 9
    k_aggh2<false, false><<<g_agg2g, TB>>>((const uint2*)hs3, b3, dout, n);       // 10
}

// round 13
// speedup vs baseline: 1.2148x; 1.2148x over previous
#include <cuda_runtime.h>
#include <cuda_fp16.h>
#include <mma.h>
#include <math.h>

using namespace nvcuda;

#define NMAX   100000
#define EMAX   1600000
#define SCAN_B 512

// Static scratch ~59 MB.
__device__ float g_y[(size_t)NMAX * 128];   // persistent feature buffer
__device__ float g_dinv[NMAX];
__device__ int   g_dc[2 * NMAX];            // [0:N) deg, [N:2N) cursor — one memset
__device__ int   g_rowptr[NMAX];
__device__ int   g_csr[EMAX];
__device__ int   g_bsums[1024];
// split-fp16 weights (hi + lo residual)
__device__ __half g_w2h[128 * 64], g_w2l[128 * 64];
__device__ __half g_w3h[64 * 64],  g_w3l[64 * 64];

// ---------------- degree count + fused weight convert ----------------
__global__ void k_deg_count(const int* __restrict__ dst, int E,
                            const float* __restrict__ W2, const float* __restrict__ W3) {
    int e = blockIdx.x * blockDim.x + threadIdx.x;
    if (e < E) atomicAdd(&g_dc[__ldg(dst + e)], 1);
    if (blockIdx.x < 32) {
        int i = blockIdx.x * blockDim.x + threadIdx.x;
        if (i < 128 * 64) {
            float w = W2[i];
            __half h = __float2half_rn(w);
            g_w2h[i] = h;
            g_w2l[i] = __float2half_rn(w - __half2float(h));
        }
        if (i < 64 * 64) {
            float w = W3[i];
            __half h = __float2half_rn(w);
            g_w3h[i] = h;
            g_w3l[i] = __float2half_rn(w - __half2float(h));
        }
    }
}

// ---------------- multi-block warp-shuffle scan + dinv / + xscale ----------------
__global__ void k_scan1(int n) {
    __shared__ int wsum[SCAN_B / 32];
    int gid = blockIdx.x * SCAN_B + threadIdx.x;
    int v = (gid < n) ? g_dc[gid] : 0;
    if (gid < n) g_dinv[gid] = rsqrtf((float)(v + 1));  // +1 self loop
    int lane = threadIdx.x & 31, wid = threadIdx.x >> 5;
    int incl = v;
#pragma unroll
    for (int o = 1; o < 32; o <<= 1) {
        int t = __shfl_up_sync(0xffffffffu, incl, o);
        if (lane >= o) incl += t;
    }
    if (lane == 31) wsum[wid] = incl;
    __syncthreads();
    if (wid == 0) {
        int s = (lane < SCAN_B / 32) ? wsum[lane] : 0;
#pragma unroll
        for (int o = 1; o < SCAN_B / 32; o <<= 1) {
            int t = __shfl_up_sync(0xffffffffu, s, o);
            if (lane >= o) s += t;
        }
        if (lane < SCAN_B / 32) wsum[lane] = s;
    }
    __syncthreads();
    int off = wid ? wsum[wid - 1] : 0;
    if (gid < n) g_rowptr[gid] = off + incl - v;  // exclusive
    if (threadIdx.x == SCAN_B - 1) g_bsums[blockIdx.x] = off + incl;
}

__global__ void k_scan2(int nb) {  // single block, nb <= SCAN_B
    __shared__ int sm[SCAN_B];
    int v = (threadIdx.x < nb) ? g_bsums[threadIdx.x] : 0;
    sm[threadIdx.x] = v;
    __syncthreads();
    for (int off = 1; off < SCAN_B; off <<= 1) {
        int t = (threadIdx.x >= off) ? sm[threadIdx.x - off] : 0;
        __syncthreads();
        sm[threadIdx.x] += t;
        __syncthreads();
    }
    if (threadIdx.x < nb) g_bsums[threadIdx.x] = sm[threadIdx.x];  // inclusive
}

// scan3 + xscale: finalize rowptr offsets AND emit xs = x*dinv as fp16
__global__ void k_scan3x(const float* __restrict__ x, __half2* __restrict__ xs, int n) {
    int gid = blockIdx.x * SCAN_B + threadIdx.x;
    if (gid >= n) return;
    if (blockIdx.x > 0) g_rowptr[gid] += g_bsums[blockIdx.x - 1];
    float dv = g_dinv[gid];
    float v[16];
#pragma unroll
    for (int c = 0; c < 13; ++c) v[c] = x[(size_t)gid * 13 + c] * dv;
#pragma unroll
    for (int c = 13; c < 16; ++c) v[c] = 0.0f;
#pragma unroll
    for (int p = 0; p < 8; ++p)
        xs[(size_t)gid * 8 + p] = __floats2half2_rn(v[2 * p], v[2 * p + 1]);
}

// ---------------- CSR placement ----------------
__global__ void k_place(const int* __restrict__ src, const int* __restrict__ dst, int E) {
    int e = blockIdx.x * blockDim.x + threadIdx.x;
    if (e >= E) return;
    int d = __ldg(dst + e);
    int pos = g_rowptr[d] + atomicAdd(&g_dc[NMAX + d], 1);
    g_csr[pos] = __ldg(src + e);
}

// ---------------- 13(16)-ch aggregation: 8 neighbors per load-instruction ----------------
// group g=lane>>2 owns neighbor t+g; cl=lane&3 loads uint2 (channels 4cl..4cl+3).
__global__ void k_agg13(const uint2* __restrict__ xs, float* __restrict__ xa, int n) {
    int node = blockIdx.x * (blockDim.x >> 5) + (threadIdx.x >> 5);
    int lane = threadIdx.x & 31;
    if (node >= n) return;
    const int g = lane >> 2;
    const int cl = lane & 3;

    float a0 = 0, a1 = 0, a2 = 0, a3 = 0;
    if (g == 0) {  // self term once
        uint2 u = __ldg(&xs[(size_t)node * 4 + cl]);
        float2 f0 = __half22float2(*(__half2*)&u.x);
        float2 f1 = __half22float2(*(__half2*)&u.y);
        a0 = f0.x; a1 = f0.y; a2 = f1.x; a3 = f1.y;
    }
    int start = g_rowptr[node];
    int end = start + g_dc[node];

    for (int j0 = start; j0 < end; j0 += 32) {
        int idx = 0;
        if (j0 + lane < end) idx = __ldg(&g_csr[j0 + lane]);
        int cnt = min(32, end - j0);
        int t = 0;
        for (; t + 16 <= cnt; t += 16) {  // 2 loads in flight
            int s0 = __shfl_sync(0xffffffffu, idx, t + g);
            int s1 = __shfl_sync(0xffffffffu, idx, t + 8 + g);
            uint2 u0 = __ldg(&xs[(size_t)s0 * 4 + cl]);
            uint2 u1 = __ldg(&xs[(size_t)s1 * 4 + cl]);
            float2 f00 = __half22float2(*(__half2*)&u0.x);
            float2 f01 = __half22float2(*(__half2*)&u0.y);
            float2 f10 = __half22float2(*(__half2*)&u1.x);
            float2 f11 = __half22float2(*(__half2*)&u1.y);
            a0 += f00.x + f10.x; a1 += f00.y + f10.y;
            a2 += f01.x + f11.x; a3 += f01.y + f11.y;
        }
        if (t + 8 <= cnt) {
            int s = __shfl_sync(0xffffffffu, idx, t + g);
            uint2 u = __ldg(&xs[(size_t)s * 4 + cl]);
            float2 f0 = __half22float2(*(__half2*)&u.x);
            float2 f1 = __half22float2(*(__half2*)&u.y);
            a0 += f0.x; a1 += f0.y; a2 += f1.x; a3 += f1.y;
            t += 8;
        }
        int rem = cnt - t;
        if (rem > 0) {
            int s = __shfl_sync(0xffffffffu, idx, t + (g < rem ? g : 0));
            if (g < rem) {
                uint2 u = __ldg(&xs[(size_t)s * 4 + cl]);
                float2 f0 = __half22float2(*(__half2*)&u.x);
                float2 f1 = __half22float2(*(__half2*)&u.y);
                a0 += f0.x; a1 += f0.y; a2 += f1.x; a3 += f1.y;
            }
        }
    }
    // reduce across the 8 groups
#pragma unroll
    for (int off = 16; off >= 4; off >>= 1) {
        a0 += __shfl_down_sync(0xffffffffu, a0, off);
        a1 += __shfl_down_sync(0xffffffffu, a1, off);
        a2 += __shfl_down_sync(0xffffffffu, a2, off);
        a3 += __shfl_down_sync(0xffffffffu, a3, off);
    }
    if (lane < 4) {
        float dv = g_dinv[node];
        *(float4*)&xa[(size_t)node * 16 + cl * 4] =
            make_float4(a0 * dv, a1 * dv, a2 * dv, a3 * dv);
    }
}

// ---------------- layer-1 scalar GEMM (fp32 in, fp16 out, bias+relu) ----------------
__global__ void k_gemm_l1(const float* __restrict__ x,
                          const float* __restrict__ W,
                          const float* __restrict__ bias,
                          __half* __restrict__ hout, int n) {
    constexpr int TB = 256, CIN = 13, COUT = 128, ROWS = 32, ITER = 8;
    constexpr int CPT = COUT / 16;  // 8
    constexpr int SXS = 20;
    __shared__ float Ws[CIN * COUT];
    __shared__ float xs[ROWS * SXS];

    {
        const float4* Wv = (const float4*)W;
        for (int i = threadIdx.x; i < CIN * COUT / 4; i += TB)
            ((float4*)Ws)[i] = Wv[i];
    }
    const int cg = threadIdx.x & 15;
    const int rg = threadIdx.x >> 4;
    float bb[CPT];
#pragma unroll
    for (int j = 0; j < CPT; ++j) bb[j] = __ldg(bias + cg * CPT + j);

    for (int it = 0; it < ITER; ++it) {
        const int rowbase = (blockIdx.x * ITER + it) * ROWS;
        if (rowbase >= n) break;
        float acc[2][CPT];
#pragma unroll
        for (int j = 0; j < CPT; ++j) { acc[0][j] = bb[j]; acc[1][j] = bb[j]; }

        __syncthreads();
        for (int i = threadIdx.x; i < ROWS * CIN; i += TB) {
            int row = i / CIN, c = i % CIN;
            int rr = rowbase + row;
            xs[row * SXS + c] = (rr < n) ? x[(size_t)rr * 16 + c] : 0.0f;
        }
        __syncthreads();
        const float* wbase = Ws + cg * CPT;
        const float* x0 = xs + (2 * rg) * SXS;
        const float* x1 = x0 + SXS;
#pragma unroll
        for (int k = 0; k < CIN; ++k) {
            float a0 = x0[k], a1 = x1[k];
            const float4* wr = (const float4*)(wbase + k * COUT);
#pragma unroll
            for (int j4 = 0; j4 < CPT / 4; ++j4) {
                float4 w = wr[j4];
                acc[0][j4 * 4 + 0] = fmaf(a0, w.x, acc[0][j4 * 4 + 0]);
                acc[0][j4 * 4 + 1] = fmaf(a0, w.y, acc[0][j4 * 4 + 1]);
                acc[0][j4 * 4 + 2] = fmaf(a0, w.z, acc[0][j4 * 4 + 2]);
                acc[0][j4 * 4 + 3] = fmaf(a0, w.w, acc[0][j4 * 4 + 3]);
                acc[1][j4 * 4 + 0] = fmaf(a1, w.x, acc[1][j4 * 4 + 0]);
                acc[1][j4 * 4 + 1] = fmaf(a1, w.y, acc[1][j4 * 4 + 1]);
                acc[1][j4 * 4 + 2] = fmaf(a1, w.z, acc[1][j4 * 4 + 2]);
                acc[1][j4 * 4 + 3] = fmaf(a1, w.w, acc[1][j4 * 4 + 3]);
            }
        }
#pragma unroll
        for (int rr = 0; rr < 2; ++rr) {
            int r = rowbase + 2 * rg + rr;
            if (r >= n) continue;
            __half2* hp = (__half2*)(hout + (size_t)r * 128 + cg * CPT);
#pragma unroll
            for (int j2 = 0; j2 < CPT / 2; ++j2)
                hp[j2] = __floats2half2_rn(fmaxf(acc[rr][j2 * 2], 0.0f),
                                           fmaxf(acc[rr][j2 * 2 + 1], 0.0f));
        }
    }
}

// ---------------- tensor-core GEMM (fp16 in, split-fp16 W, fp32 acc, fp16*dinv out) ----------------
template <int CIN>
__global__ void k_gemm_tc(const __half* __restrict__ A, int lda,
                          const __half* __restrict__ Whi, const __half* __restrict__ Wlo,
                          __half* __restrict__ hout, int ldo, int n) {
    constexpr int KT = CIN / 16;
    constexpr int WS_BYTES = 2 * CIN * 64 * 2;
    constexpr int EP_BYTES = 8 * 16 * 68 * 4;
    constexpr int SM_BYTES = (WS_BYTES > EP_BYTES) ? WS_BYTES : EP_BYTES;
    __shared__ __align__(16) unsigned char smem_raw[SM_BYTES];
    __half* Ws = (__half*)smem_raw;
    float* ep = (float*)smem_raw;

    for (int i = threadIdx.x; i < CIN * 64; i += 256) {
        Ws[i] = Whi[i];
        Ws[CIN * 64 + i] = Wlo[i];
    }
    __syncthreads();

    const int warp = threadIdx.x >> 5;
    const int lane = threadIdx.x & 31;
    const int rowbase = blockIdx.x * 128 + warp * 16;

    wmma::fragment<wmma::accumulator, 16, 16, 16, float> acc[4];
#pragma unroll
    for (int nt = 0; nt < 4; ++nt) wmma::fill_fragment(acc[nt], 0.0f);

    if (rowbase < n) {
#pragma unroll
        for (int kt = 0; kt < KT; ++kt) {
            wmma::fragment<wmma::matrix_a, 16, 16, 16, __half, wmma::row_major> af;
            wmma::load_matrix_sync(af, A + (size_t)rowbase * lda + kt * 16, lda);
#pragma unroll
            for (int nt = 0; nt < 4; ++nt) {
                wmma::fragment<wmma::matrix_b, 16, 16, 16, __half, wmma::row_major> bh, bl;
                wmma::load_matrix_sync(bh, Ws + kt * 16 * 64 + nt * 16, 64);
                wmma::mma_sync(acc[nt], af, bh, acc[nt]);
                wmma::load_matrix_sync(bl, Ws + CIN * 64 + kt * 16 * 64 + nt * 16, 64);
                wmma::mma_sync(acc[nt], af, bl, acc[nt]);
            }
        }
    }
    __syncthreads();

    float* myep = ep + warp * 16 * 68;
#pragma unroll
    for (int nt = 0; nt < 4; ++nt)
        wmma::store_matrix_sync(myep + nt * 16, acc[nt], 68, wmma::mem_row_major);
    __syncwarp();

    if (rowbase < n) {
#pragma unroll
        for (int r = 0; r < 16; ++r) {
            int gr = rowbase + r;
            if (gr >= n) break;
            float dv = g_dinv[gr];
            float vx = myep[r * 68 + lane * 2];
            float vy = myep[r * 68 + lane * 2 + 1];
            ((__half2*)(hout + (size_t)gr * ldo))[lane] = __floats2half2_rn(vx * dv, vy * dv);
        }
    }
}

// ---------------- 64-ch aggregation: 2 neighbors per load-instruction, 1 node/warp ----------------
// hf=lane>>4 owns neighbor t+hf; hl=lane&15 loads uint2 (channels 4hl..4hl+3).
template <bool RELU, bool OUT_HALF>
__global__ void k_aggh(const uint2* __restrict__ hs,
                       const float* __restrict__ b,
                       void* __restrict__ yout, int n) {
    int node = blockIdx.x * (blockDim.x >> 5) + (threadIdx.x >> 5);
    int lane = threadIdx.x & 31;
    if (node >= n) return;
    const int hf = lane >> 4;
    const int hl = lane & 15;

    float a0 = 0, a1 = 0, a2 = 0, a3 = 0;
    if (hf == 0) {  // self term once
        uint2 u = __ldg(&hs[(size_t)node * 16 + hl]);
        float2 f0 = __half22float2(*(__half2*)&u.x);
        float2 f1 = __half22float2(*(__half2*)&u.y);
        a0 = f0.x; a1 = f0.y; a2 = f1.x; a3 = f1.y;
    }
    int start = g_rowptr[node];
    int end = start + g_dc[node];

    for (int j0 = start; j0 < end; j0 += 32) {
        int idx = 0;
        if (j0 + lane < end) idx = __ldg(&g_csr[j0 + lane]);
        int cnt = min(32, end - j0);
        int t = 0;
        for (; t + 8 <= cnt; t += 8) {  // 4 loads in flight, 8 neighbors
            uint2 uu[4];
#pragma unroll
            for (int u = 0; u < 4; ++u) {
                int s = __shfl_sync(0xffffffffu, idx, t + 2 * u + hf);
                uu[u] = __ldg(&hs[(size_t)s * 16 + hl]);
            }
#pragma unroll
            for (int u = 0; u < 4; ++u) {
                float2 f0 = __half22float2(*(__half2*)&uu[u].x);
                float2 f1 = __half22float2(*(__half2*)&uu[u].y);
                a0 += f0.x; a1 += f0.y; a2 += f1.x; a3 += f1.y;
            }
        }
        for (; t + 2 <= cnt; t += 2) {
            int s = __shfl_sync(0xffffffffu, idx, t + hf);
            uint2 u = __ldg(&hs[(size_t)s * 16 + hl]);
            float2 f0 = __half22float2(*(__half2*)&u.x);
            float2 f1 = __half22float2(*(__half2*)&u.y);
            a0 += f0.x; a1 += f0.y; a2 += f1.x; a3 += f1.y;
        }
        if (t < cnt) {  // one leftover neighbor — half 0 only
            int s = __shfl_sync(0xffffffffu, idx, t);
            if (hf == 0) {
                uint2 u = __ldg(&hs[(size_t)s * 16 + hl]);
                float2 f0 = __half22float2(*(__half2*)&u.x);
                float2 f1 = __half22float2(*(__half2*)&u.y);
                a0 += f0.x; a1 += f0.y; a2 += f1.x; a3 += f1.y;
            }
        }
    }
    // combine the two halves
    a0 += __shfl_down_sync(0xffffffffu, a0, 16);
    a1 += __shfl_down_sync(0xffffffffu, a1, 16);
    a2 += __shfl_down_sync(0xffffffffu, a2, 16);
    a3 += __shfl_down_sync(0xffffffffu, a3, 16);

    if (lane < 16) {
        float dv = g_dinv[node];
        float4 bb = *(const float4*)(b + hl * 4);
        float o0 = fmaf(a0, dv, bb.x);
        float o1 = fmaf(a1, dv, bb.y);
        float o2 = fmaf(a2, dv, bb.z);
        float o3 = fmaf(a3, dv, bb.w);
        if (RELU) {
            o0 = fmaxf(o0, 0.0f); o1 = fmaxf(o1, 0.0f);
            o2 = fmaxf(o2, 0.0f); o3 = fmaxf(o3, 0.0f);
        }
        if (OUT_HALF) {
            uint2 w;
            *(__half2*)&w.x = __floats2half2_rn(o0, o1);
            *(__half2*)&w.y = __floats2half2_rn(o2, o3);
            ((uint2*)yout)[(size_t)node * 16 + hl] = w;
        } else {
            *(float4*)&((float*)yout)[(size_t)node * 64 + hl * 4] =
                make_float4(o0, o1, o2, o3);
        }
    }
}

// ---------------- launch ----------------
extern "C" void kernel_launch(void* const* d_in, const int* in_sizes, int n_in,
                              void* d_out, int out_size) {
    const float* x  = (const float*)d_in[0];
    const int*   ei = (const int*)d_in[1];
    const float* W1 = (const float*)d_in[2];
    const float* b1 = (const float*)d_in[3];
    const float* W2 = (const float*)d_in[4];
    const float* b2 = (const float*)d_in[5];
    const float* W3 = (const float*)d_in[6];
    const float* b3 = (const float*)d_in[7];
    float* dout = (float*)d_out;

    const int n = in_sizes[0] / 13;
    const int E = in_sizes[1] / 2;
    const int* src = ei;
    const int* dst = ei + E;

    const int TB = 256;
    auto cdiv = [](long long a, long long b) { return (int)((a + b - 1) / b); };
    const int g_aggg = cdiv(n, TB / 32);
    const int g_tc = cdiv(n, 128);
    const int nb = cdiv(n, SCAN_B);

    float* y = nullptr;
    cudaGetSymbolAddress((void**)&y, g_y);
    int* dcp = nullptr;
    cudaGetSymbolAddress((void**)&dcp, g_dc);
    __half *w2h, *w2l, *w3h, *w3l;
    cudaGetSymbolAddress((void**)&w2h, g_w2h);
    cudaGetSymbolAddress((void**)&w2l, g_w2l);
    cudaGetSymbolAddress((void**)&w3h, g_w3h);
    cudaGetSymbolAddress((void**)&w3l, g_w3l);

    // Buffer plan (sequential stream, dead-before-overwrite):
    __half2* xs_h2 = (__half2*)dout;                    // N x 8 half2
    float*   xa    = dout + (size_t)n * 8;              // N x 16 fp32
    __half*  y1h   = (__half*)y;                        // N x 128 fp16
    __half*  hs2   = (__half*)dout;                     // N x 64 fp16
    __half*  y2h   = (__half*)(y + (size_t)NMAX * 64);  // N x 64 fp16
    __half*  hs3   = (__half*)y;                        // N x 64 fp16 (over dead y1h)

    // ---- CSR build ----
    cudaMemsetAsync(dcp, 0, (size_t)2 * NMAX * 4, 0);           // 1
    k_deg_count<<<cdiv(E, TB), TB>>>(dst, E, W2, W3);           // 2 (+wconv)
    k_scan1<<<nb, SCAN_B>>>(n);                                 // 3 (+dinv)
    k_scan2<<<1, SCAN_B>>>(nb);                                 // 4
    k_scan3x<<<nb, SCAN_B>>>(x, xs_h2, n);                      // 5 (+xscale)
    k_place<<<cdiv(E, TB), TB>>>(src, dst, E);                  // 6

    // ---- layer 1 ----
    k_agg13<<<g_aggg, TB>>>((const uint2*)xs_h2, xa, n);        // 7
    k_gemm_l1<<<cdiv(n, 32 * 8), TB>>>(xa, W1, b1, y1h, n);     // 8

    // ---- layer 2 ----
    k_gemm_tc<128><<<g_tc, TB>>>(y1h, 128, w2h, w2l, hs2, 64, n);               // 9
    k_aggh<true, true><<<g_aggg, TB>>>((const uint2*)hs2, b2, y2h, n);          // 10

    // ---- layer 3 ----
    k_gemm_tc<64><<<g_tc, TB>>>(y2h, 64, w3h, w3l, hs3, 64, n);                 // 11
    k_aggh<false, false><<<g_aggg, TB>>>((const uint2*)hs3, b3, dout, n);       // 12
}